// round 17
// baseline (speedup 1.0000x reference)
#include <cuda_runtime.h>
#include <cstdint>

#define N_NODES 100000
#define N_EDGES 800000
#define NGRAPH  512
#define NLAYER  3
#define NB_STAT 1184
#define TB      256

// ---------------- static scratch ----------------
__device__ float g_h   [N_NODES * 64];
__device__ float g_Pa  [N_NODES * 32];
__device__ float g_Pb  [N_NODES * 32];
__device__ float g_agg [NLAYER][N_NODES * 64];
__device__ float g_z1n [N_NODES * 32];
__device__ float g_a2n [N_NODES * 64];
__device__ float g_deg [N_NODES];
__device__ float g_pool[NGRAPH * 64];
__device__ float g_cnt [NGRAPH];
__device__ float g_stat[12][128];   // per-BN-phase stat slots: [0..63]=sum, [64..127]=sumsq
__device__ uint2 g_Blo [1024];      // W2 low-order tf32 fragments (built per layer by k_edge_a)

// ---------------- helpers ----------------
__device__ __forceinline__ void red2(float* p, float a, float b) {
    asm volatile("red.global.add.v2.f32 [%0], {%1, %2};"
                 :: "l"(p), "f"(a), "f"(b) : "memory");
}
__device__ __forceinline__ void red1(float* p, float a) {
    asm volatile("red.global.add.f32 [%0], %1;"
                 :: "l"(p), "f"(a) : "memory");
}
__device__ __forceinline__ uint32_t f2tf32(float x) {
    uint32_t r; asm("cvt.rna.tf32.f32 %0, %1;" : "=r"(r) : "f"(x)); return r;
}
__device__ __forceinline__ void mma_tf32(float& c0, float& c1, float& c2, float& c3,
                                         uint32_t a0, uint32_t a1, uint32_t a2, uint32_t a3,
                                         uint32_t b0, uint32_t b1) {
    asm volatile("mma.sync.aligned.m16n8k8.row.col.f32.tf32.tf32.f32 "
                 "{%0,%1,%2,%3}, {%4,%5,%6,%7}, {%8,%9}, {%0,%1,%2,%3};"
                 : "+f"(c0), "+f"(c1), "+f"(c2), "+f"(c3)
                 : "r"(a0), "r"(a1), "r"(a2), "r"(a3), "r"(b0), "r"(b1));
}

// ---------------- zero accumulated scratch (incl. stat slots) ----------------
__global__ void k_zero() {
    long i  = (long)blockIdx.x * blockDim.x + threadIdx.x;
    long st = (long)gridDim.x * blockDim.x;
    float* aggf = &g_agg[0][0];
    long tot = (long)NLAYER * N_NODES * 64;
    for (long j = i; j < tot; j += st) aggf[j] = 0.f;
    for (long j = i; j < N_NODES; j += st) g_deg[j] = 0.f;
    for (long j = i; j < NGRAPH * 64; j += st) g_pool[j] = 0.f;
    for (long j = i; j < NGRAPH; j += st) g_cnt[j] = 0.f;
    if (i < 12 * 128) (&g_stat[0][0])[i] = 0.f;
}

// ---------------- producer epilogue: block-reduce + atomic into stat slot ----------------
__device__ __forceinline__ void stat_epilogue(float (*red)[128], float* slot) {
    __syncthreads();
    int f = threadIdx.x;
    if (f < 128) {
        float S = 0.f;
#pragma unroll
        for (int w = 0; w < 8; w++) S += red[w][f];
        red1(slot + f, S);
    }
}

// ---------------- consumer prologue: fold stats into (s,t) per block ----------------
__device__ __forceinline__ void bn_prologue(const float* __restrict__ slot,
                                            const float* __restrict__ gam,
                                            const float* __restrict__ bet,
                                            double invcnt, int nf,
                                            float* sS, float* sT) {
    int f = threadIdx.x;
    if (f < nf) {
        double S = (double)slot[f];
        double Q = (double)slot[64 + f];
        double m = S * invcnt;
        double v = Q * invcnt - m * m;
        if (v < 0.0) v = 0.0;
        double inv = rsqrt(v + 1e-5);
        float sc = (float)((double)__ldg(gam + f) * inv);
        sS[f] = sc;
        sT[f] = __ldg(bet + f) - (float)m * sc;
    }
}

// ---------------- project h -> Pa,Pb (LDS.128 broadcast GEMM, scalar FMA) ----------------
__device__ __forceinline__ void project_group(const float* __restrict__ W1, int lane,
                                              float* ht, const float h0[4], const float h1[4],
                                              int base) {
    __syncwarp();
    ((float4*)ht)[lane]      = make_float4(h0[0], h0[1], h0[2], h0[3]);
    ((float4*)ht)[lane + 32] = make_float4(h1[0], h1[1], h1[2], h1[3]);
    __syncwarp();
    float pa[4] = {0, 0, 0, 0}, pb[4] = {0, 0, 0, 0};
#pragma unroll 16
    for (int k = 0; k < 64; k++) {
        float4 hv = ((const float4*)ht)[k];
        float wa = __ldg(W1 + k * 32 + lane);
        float wb = __ldg(W1 + (64 + k) * 32 + lane);
        pa[0] = fmaf(hv.x, wa, pa[0]); pb[0] = fmaf(hv.x, wb, pb[0]);
        pa[1] = fmaf(hv.y, wa, pa[1]); pb[1] = fmaf(hv.y, wb, pb[1]);
        pa[2] = fmaf(hv.z, wa, pa[2]); pb[2] = fmaf(hv.z, wb, pb[2]);
        pa[3] = fmaf(hv.w, wa, pa[3]); pb[3] = fmaf(hv.w, wb, pb[3]);
    }
#pragma unroll
    for (int i = 0; i < 4; i++) {
        g_Pa[(base + i) * 32 + lane] = pa[i];
        g_Pb[(base + i) * 32 + lane] = pb[i];
    }
}

// ---------------- fused: h = x @ Win + b, then Pa/Pb projection (layer 0) ----------------
__global__ void __launch_bounds__(TB) k_lin_proj(const float* __restrict__ x,
                                                 const float* __restrict__ Wi,
                                                 const float* __restrict__ bi,
                                                 const float* __restrict__ W1) {
    __shared__ float hT[8][256];
    int lane = threadIdx.x & 31, wib = threadIdx.x >> 5;
    int warp = (blockIdx.x * TB + threadIdx.x) >> 5;
    int nw   = (gridDim.x * TB) >> 5;
    float b0 = __ldg(bi + lane), b1 = __ldg(bi + 32 + lane);
    float* ht = hT[wib];
    for (int grp = warp; grp < N_NODES / 4; grp += nw) {
        int base = grp * 4;
        float h0[4], h1[4];
#pragma unroll
        for (int i = 0; i < 4; i++) {
            int n = base + i;
            float a0 = b0, a1 = b1;
#pragma unroll
            for (int k = 0; k < 16; k++) {
                float xv = __ldg(x + n * 16 + k);
                a0 = fmaf(xv, __ldg(Wi + k * 64 + lane), a0);
                a1 = fmaf(xv, __ldg(Wi + k * 64 + 32 + lane), a1);
            }
            h0[i] = a0; h1[i] = a1;
            g_h[n * 64 + lane] = a0;
            g_h[n * 64 + 32 + lane] = a1;
        }
        project_group(W1, lane, ht, h0, h1, base);
    }
}

// ---------------- edge pass A: stats of z1; build W2 Blo fragments; deg on layer0 ----------------
__global__ void __launch_bounds__(TB) k_edge_a(const int* __restrict__ dst,
                                               const int* __restrict__ src,
                                               const float* __restrict__ ea,
                                               const float* __restrict__ W1,
                                               const float* __restrict__ b1,
                                               const float* __restrict__ W2,
                                               float* slot_m1, int do_deg) {
    __shared__ float red[8][128];
    int lane = threadIdx.x & 31, wib = threadIdx.x >> 5;
    int warp = (blockIdx.x * TB + threadIdx.x) >> 5;
    int nw   = (gridDim.x * TB) >> 5;

    // block 0, warp 0: build low-order tf32 fragments of this layer's W2
    if (blockIdx.x == 0 && wib == 0) {
        int tg = lane & 3, tr = lane >> 2;
#pragma unroll 1
        for (int p = 0; p < 32; p++) {
            int s = p >> 3, j = p & 7;
            int kk = s * 8 + tg;
            int nn = j * 8 + tr;
            float w0 = __ldg(W2 + kk * 64 + nn);
            float w1 = __ldg(W2 + (kk + 4) * 64 + nn);
            uint32_t h0 = f2tf32(w0), h1 = f2tf32(w1);
            g_Blo[p * 32 + lane] = make_uint2(f2tf32(w0 - __uint_as_float(h0)),
                                              f2tf32(w1 - __uint_as_float(h1)));
        }
    }

    float cw = __ldg(W1 + 128 * 32 + lane);
    float cb = __ldg(b1 + lane);
    float S = 0.f, Q = 0.f;
    for (int grp = warp; grp < N_EDGES / 8; grp += nw) {
        int e0 = grp * 8;
        int d[8], s[8];
        float ev[8], pa[8], pb[8];
#pragma unroll
        for (int i = 0; i < 8; i++) {
            d[i] = __ldg(dst + e0 + i);
            s[i] = __ldg(src + e0 + i);
            ev[i] = __ldg(ea + e0 + i);
        }
        if (do_deg && lane < 8) {
            int dd = __ldg(dst + e0 + lane);
            red1(&g_deg[dd], 1.0f);
        }
#pragma unroll
        for (int i = 0; i < 8; i++) pa[i] = g_Pa[d[i] * 32 + lane];
#pragma unroll
        for (int i = 0; i < 8; i++) pb[i] = g_Pb[s[i] * 32 + lane];
#pragma unroll
        for (int i = 0; i < 8; i++) {
            float z = pa[i] + pb[i] + fmaf(ev[i], cw, cb);
            S += z;
            Q = fmaf(z, z, Q);
        }
    }
    red[wib][lane] = S;       red[wib][32 + lane] = 0.f;
    red[wib][64 + lane] = Q;  red[wib][96 + lane] = 0.f;
    stat_epilogue(red, slot_m1);
}

// ---------------- edge pass B: msg MLP via split-precision tf32 MMA + scatter ----------------
// Warp tile = 16 edges. A = a1[16x32] (row=edge), B = W2[32x64].
// A staged fp32, split hi/lo in registers; Bhi in smem, Blo via __ldg (prebuilt).
// D = Ahi*Bhi + Alo*Bhi + Ahi*Blo  (3xTF32, residual ~2^-22).
#define OSTRIDE 68
__global__ void __launch_bounds__(TB) k_edge_b(const int* __restrict__ dst,
                                               const int* __restrict__ src,
                                               const float* __restrict__ ea,
                                               const float* __restrict__ W1,
                                               const float* __restrict__ b1,
                                               const float* __restrict__ W2,
                                               const float* __restrict__ b2,
                                               const float* __restrict__ gam1,
                                               const float* __restrict__ bet1,
                                               const float* slot_m1,
                                               float* slot_m2,
                                               double invE, int layer) {
    __shared__ uint2 Bf[4][8][32];         // hi fragments: [kstep][ntile][lane], 8KB
    __shared__ float buf[8][16 * OSTRIDE]; // per-warp union: aS fp32 (32x24) then oS (16x68)
    __shared__ float red[8][128];
    __shared__ float sS[64], sT[64];
    int lane = threadIdx.x & 31, wib = threadIdx.x >> 5;
    int tg = lane & 3, tr = lane >> 2;
    int gwarp = (blockIdx.x * TB + threadIdx.x) >> 5;
    int nwarp = (gridDim.x * TB) >> 5;
    float* agg = &g_agg[layer][0];

    bn_prologue(slot_m1, gam1, bet1, invE, 32, sS, sT);

    // build B hi fragments
#pragma unroll
    for (int p = 0; p < 4; p++) {
        int pair = wib * 4 + p;
        int s = pair >> 3, j = pair & 7;
        int kk = s * 8 + tg;
        int nn = j * 8 + tr;
        Bf[s][j][lane] = make_uint2(f2tf32(__ldg(W2 + kk * 64 + nn)),
                                    f2tf32(__ldg(W2 + (kk + 4) * 64 + nn)));
    }

    float cw = __ldg(W1 + 128 * 32 + lane);
    float cb = __ldg(b1 + lane);
    float ss0 = 0.f, ss1 = 0.f, qq0 = 0.f, qq1 = 0.f;
    __syncthreads();
    float bs = sS[lane], bt = sT[lane];

    float* bufw = buf[wib];

    for (int tile = gwarp; tile < N_EDGES / 16; tile += nwarp) {
        int e0 = tile * 16;
        int4 d4[4];
        // stage a1 (fp32) into aS [feat][edge], stride 24
        __syncwarp();
#pragma unroll
        for (int c = 0; c < 4; c++) {
            d4[c]       = __ldg((const int4*)(dst + e0 + 4 * c));
            int4 s4     = __ldg((const int4*)(src + e0 + 4 * c));
            float4 ev4  = __ldg((const float4*)(ea + e0 + 4 * c));
            float pa0 = g_Pa[d4[c].x * 32 + lane], pb0 = g_Pb[s4.x * 32 + lane];
            float pa1 = g_Pa[d4[c].y * 32 + lane], pb1 = g_Pb[s4.y * 32 + lane];
            float pa2 = g_Pa[d4[c].z * 32 + lane], pb2 = g_Pb[s4.z * 32 + lane];
            float pa3 = g_Pa[d4[c].w * 32 + lane], pb3 = g_Pb[s4.w * 32 + lane];
            float4 av;
            av.x = fmaxf(fmaf(pa0 + pb0 + fmaf(ev4.x, cw, cb), bs, bt), 0.f);
            av.y = fmaxf(fmaf(pa1 + pb1 + fmaf(ev4.y, cw, cb), bs, bt), 0.f);
            av.z = fmaxf(fmaf(pa2 + pb2 + fmaf(ev4.z, cw, cb), bs, bt), 0.f);
            av.w = fmaxf(fmaf(pa3 + pb3 + fmaf(ev4.w, cw, cb), bs, bt), 0.f);
            ((float4*)(bufw + lane * 24))[c] = av;
        }
        __syncwarp();
        // load A fragments (fp32), split hi/lo in registers
        uint32_t ahi[4][4], alo[4][4];
#pragma unroll
        for (int s = 0; s < 4; s++) {
            float af[4];
            af[0] = bufw[(s * 8 + tg) * 24 + tr];
            af[1] = bufw[(s * 8 + tg) * 24 + tr + 8];
            af[2] = bufw[(s * 8 + tg + 4) * 24 + tr];
            af[3] = bufw[(s * 8 + tg + 4) * 24 + tr + 8];
#pragma unroll
            for (int q = 0; q < 4; q++) {
                uint32_t h = f2tf32(af[q]);
                ahi[s][q] = h;
                alo[s][q] = f2tf32(af[q] - __uint_as_float(h));
            }
        }
        __syncwarp();   // aS dead; bufw becomes oS
        // mma over 8 n-tiles, 3xTF32 per k-step
#pragma unroll
        for (int j = 0; j < 8; j++) {
            float2 bz = __ldg((const float2*)b2 + j * 4 + tg);
            float c0 = bz.x, c1 = bz.y, c2 = bz.x, c3 = bz.y;
#pragma unroll
            for (int s = 0; s < 4; s++) {
                uint2 bh = Bf[s][j][lane];
                uint2 bl = __ldg(&g_Blo[(s * 8 + j) * 32 + lane]);
                mma_tf32(c0, c1, c2, c3,
                         ahi[s][0], ahi[s][1], ahi[s][2], ahi[s][3], bh.x, bh.y);
                mma_tf32(c0, c1, c2, c3,
                         alo[s][0], alo[s][1], alo[s][2], alo[s][3], bh.x, bh.y);
                mma_tf32(c0, c1, c2, c3,
                         ahi[s][0], ahi[s][1], ahi[s][2], ahi[s][3], bl.x, bl.y);
            }
            c0 = fmaxf(c0, 0.f); c1 = fmaxf(c1, 0.f);
            c2 = fmaxf(c2, 0.f); c3 = fmaxf(c3, 0.f);
            *(float2*)(bufw + tr * OSTRIDE + j * 8 + 2 * tg)       = make_float2(c0, c1);
            *(float2*)(bufw + (tr + 8) * OSTRIDE + j * 8 + 2 * tg) = make_float2(c2, c3);
        }
        __syncwarp();
        // stats + scatter (lane = feature pair 2*lane, 2*lane+1)
        const int* dE = (const int*)d4;
#pragma unroll
        for (int e = 0; e < 16; e++) {
            float2 o = *(const float2*)(bufw + e * OSTRIDE + 2 * lane);
            ss0 += o.x; qq0 = fmaf(o.x, o.x, qq0);
            ss1 += o.y; qq1 = fmaf(o.y, o.y, qq1);
            red2(agg + dE[e] * 64 + 2 * lane, o.x, o.y);
        }
    }
    red[wib][2 * lane]      = ss0;
    red[wib][2 * lane + 1]  = ss1;
    red[wib][64 + 2 * lane] = qq0;
    red[wib][65 + 2 * lane] = qq1;
    stat_epilogue(red, slot_m2);
}

// ---------------- node pass A: consume m2; z1n GEMM; produce u1 ----------------
__global__ void __launch_bounds__(TB) k_node_a(const float* __restrict__ U1,
                                               const float* __restrict__ ub1,
                                               const float* __restrict__ gam2,
                                               const float* __restrict__ bet2,
                                               const float* slot_m2,
                                               float* slot_u1,
                                               double invE, int layer) {
    __shared__ float xT[8][512];
    __shared__ float red[8][128];
    __shared__ float sS[64], sT[64];
    int lane = threadIdx.x & 31, wib = threadIdx.x >> 5;
    int warp = (blockIdx.x * TB + threadIdx.x) >> 5;
    int nw   = (gridDim.x * TB) >> 5;
    const float* agg = &g_agg[layer][0];

    bn_prologue(slot_m2, gam2, bet2, invE, 64, sS, sT);
    float bbz = __ldg(ub1 + lane);
    __syncthreads();
    float s2a = sS[lane], s2b = sS[lane + 32];
    float t2a = sT[lane], t2b = sT[lane + 32];

    float S = 0.f, Q = 0.f;
    float* xt = xT[wib];
    for (int grp = warp; grp < N_NODES / 4; grp += nw) {
        int base = grp * 4;
        float h0[4], h1[4], a0[4], a1[4];
#pragma unroll
        for (int i = 0; i < 4; i++) {
            int n = base + i;
            h0[i] = g_h[n * 64 + lane];
            h1[i] = g_h[n * 64 + 32 + lane];
            float dg = g_deg[n];
            a0[i] = fmaf(s2a, agg[n * 64 + lane],      t2a * dg);
            a1[i] = fmaf(s2b, agg[n * 64 + 32 + lane], t2b * dg);
        }
        __syncwarp();
        ((float4*)xt)[lane]      = make_float4(h0[0], h0[1], h0[2], h0[3]);
        ((float4*)xt)[lane + 32] = make_float4(h1[0], h1[1], h1[2], h1[3]);
        ((float4*)xt)[lane + 64] = make_float4(a0[0], a0[1], a0[2], a0[3]);
        ((float4*)xt)[lane + 96] = make_float4(a1[0], a1[1], a1[2], a1[3]);
        __syncwarp();
        float z[4] = {bbz, bbz, bbz, bbz};
#pragma unroll 16
        for (int k = 0; k < 128; k++) {
            float4 xv = ((const float4*)xt)[k];
            float w = __ldg(U1 + k * 32 + lane);
            z[0] = fmaf(xv.x, w, z[0]);
            z[1] = fmaf(xv.y, w, z[1]);
            z[2] = fmaf(xv.z, w, z[2]);
            z[3] = fmaf(xv.w, w, z[3]);
        }
#pragma unroll
        for (int i = 0; i < 4; i++) {
            g_z1n[(base + i) * 32 + lane] = z[i];
            S += z[i];
            Q = fmaf(z[i], z[i], Q);
        }
    }
    red[wib][lane] = S;       red[wib][32 + lane] = 0.f;
    red[wib][64 + lane] = Q;  red[wib][96 + lane] = 0.f;
    stat_epilogue(red, slot_u1);
}

// ---------------- node pass B: consume u1; produce u2 ----------------
__global__ void __launch_bounds__(TB) k_node_b(const float* __restrict__ U2,
                                               const float* __restrict__ ub2,
                                               const float* __restrict__ gam1,
                                               const float* __restrict__ bet1,
                                               const float* slot_u1,
                                               float* slot_u2,
                                               double invN) {
    __shared__ float U2s[2048];
    __shared__ float aT[8][2][128];
    __shared__ float red[8][128];
    __shared__ float sS[64], sT[64];
    int lane = threadIdx.x & 31, wib = threadIdx.x >> 5;
    int warp = (blockIdx.x * TB + threadIdx.x) >> 5;
    int nw   = (gridDim.x * TB) >> 5;

    bn_prologue(slot_u1, gam1, bet1, invN, 32, sS, sT);
    for (int i = threadIdx.x; i < 2048; i += TB) U2s[i] = __ldg(U2 + i);
    float2 bb = __ldg((const float2*)ub2 + lane);
    float ss0 = 0.f, ss1 = 0.f, qq0 = 0.f, qq1 = 0.f;
    __syncthreads();
    float s3 = sS[lane], t3 = sT[lane];

    int toggle = 0;
    for (int grp = warp; grp < N_NODES / 4; grp += nw) {
        int base = grp * 4;
        float a[4];
#pragma unroll
        for (int i = 0; i < 4; i++)
            a[i] = fmaxf(fmaf(g_z1n[(base + i) * 32 + lane], s3, t3), 0.f);
        float* at = aT[wib][toggle];
        ((float4*)at)[lane] = make_float4(a[0], a[1], a[2], a[3]);
        __syncwarp();
        float o00 = bb.x, o01 = bb.y, o10 = bb.x, o11 = bb.y;
        float o20 = bb.x, o21 = bb.y, o30 = bb.x, o31 = bb.y;
#pragma unroll
        for (int k = 0; k < 32; k++) {
            float4 av = ((const float4*)at)[k];
            float2 w = ((const float2*)U2s)[k * 32 + lane];
            o00 = fmaf(av.x, w.x, o00); o01 = fmaf(av.x, w.y, o01);
            o10 = fmaf(av.y, w.x, o10); o11 = fmaf(av.y, w.y, o11);
            o20 = fmaf(av.z, w.x, o20); o21 = fmaf(av.z, w.y, o21);
            o30 = fmaf(av.w, w.x, o30); o31 = fmaf(av.w, w.y, o31);
        }
        toggle ^= 1;
        o00 = fmaxf(o00, 0.f); o01 = fmaxf(o01, 0.f);
        o10 = fmaxf(o10, 0.f); o11 = fmaxf(o11, 0.f);
        o20 = fmaxf(o20, 0.f); o21 = fmaxf(o21, 0.f);
        o30 = fmaxf(o30, 0.f); o31 = fmaxf(o31, 0.f);
        ((float2*)g_a2n)[(base + 0) * 32 + lane] = make_float2(o00, o01);
        ((float2*)g_a2n)[(base + 1) * 32 + lane] = make_float2(o10, o11);
        ((float2*)g_a2n)[(base + 2) * 32 + lane] = make_float2(o20, o21);
        ((float2*)g_a2n)[(base + 3) * 32 + lane] = make_float2(o30, o31);
        ss0 += o00 + o10 + o20 + o30;
        ss1 += o01 + o11 + o21 + o31;
        qq0 = fmaf(o00, o00, fmaf(o10, o10, fmaf(o20, o20, fmaf(o30, o30, qq0))));
        qq1 = fmaf(o01, o01, fmaf(o11, o11, fmaf(o21, o21, fmaf(o31, o31, qq1))));
    }
    red[wib][2 * lane]      = ss0;
    red[wib][2 * lane + 1]  = ss1;
    red[wib][64 + 2 * lane] = qq0;
    red[wib][65 + 2 * lane] = qq1;
    stat_epilogue(red, slot_u2);
}

// ---------------- consume u2: h += bn(a2n); project next layer ----------------
__global__ void __launch_bounds__(TB) k_update_proj(const float* __restrict__ W1next,
                                                    const float* __restrict__ gam2,
                                                    const float* __restrict__ bet2,
                                                    const float* slot_u2,
                                                    double invN) {
    __shared__ float hT[8][256];
    __shared__ float sS[64], sT[64];
    int lane = threadIdx.x & 31, wib = threadIdx.x >> 5;
    int warp = (blockIdx.x * TB + threadIdx.x) >> 5;
    int nw   = (gridDim.x * TB) >> 5;
    bn_prologue(slot_u2, gam2, bet2, invN, 64, sS, sT);
    __syncthreads();
    float s4a = sS[lane], s4b = sS[lane + 32];
    float t4a = sT[lane], t4b = sT[lane + 32];
    float* ht = hT[wib];
    for (int grp = warp; grp < N_NODES / 4; grp += nw) {
        int base = grp * 4;
        float h0[4], h1[4];
#pragma unroll
        for (int i = 0; i < 4; i++) {
            int n = base + i;
            h0[i] = g_h[n * 64 + lane]      + fmaf(s4a, g_a2n[n * 64 + lane],      t4a);
            h1[i] = g_h[n * 64 + 32 + lane] + fmaf(s4b, g_a2n[n * 64 + 32 + lane], t4b);
            g_h[n * 64 + lane]      = h0[i];
            g_h[n * 64 + 32 + lane] = h1[i];
        }
        project_group(W1next, lane, ht, h0, h1, base);
    }
}

// ---------------- consume u2 (last layer): h += bn(a2n); mean-pool scatter ----------------
__global__ void __launch_bounds__(TB) k_update_pool(const int* __restrict__ batch,
                                                    const float* __restrict__ gam2,
                                                    const float* __restrict__ bet2,
                                                    const float* slot_u2,
                                                    double invN) {
    __shared__ float sS[64], sT[64];
    int lane = threadIdx.x & 31;
    int warp = (blockIdx.x * TB + threadIdx.x) >> 5;
    int nw   = (gridDim.x * TB) >> 5;
    bn_prologue(slot_u2, gam2, bet2, invN, 64, sS, sT);
    __syncthreads();
    float s4a = sS[lane], s4b = sS[lane + 32];
    float t4a = sT[lane], t4b = sT[lane + 32];
    for (int grp = warp; grp < N_NODES / 4; grp += nw) {
        int base = grp * 4;
        float h0[4], h1[4];
        int gg[4];
#pragma unroll
        for (int i = 0; i < 4; i++) {
            int n = base + i;
            h0[i] = g_h[n * 64 + lane]      + fmaf(s4a, g_a2n[n * 64 + lane],      t4a);
            h1[i] = g_h[n * 64 + 32 + lane] + fmaf(s4b, g_a2n[n * 64 + 32 + lane], t4b);
            gg[i] = __ldg(batch + n);
        }
        if (gg[0] == gg[3]) {  // batch sorted -> all four equal
            red1(&g_pool[gg[0] * 64 + lane],      h0[0] + h0[1] + h0[2] + h0[3]);
            red1(&g_pool[gg[0] * 64 + 32 + lane], h1[0] + h1[1] + h1[2] + h1[3]);
            if (lane == 0) red1(&g_cnt[gg[0]], 4.0f);
        } else {
#pragma unroll
            for (int i = 0; i < 4; i++) {
                red1(&g_pool[gg[i] * 64 + lane], h0[i]);
                red1(&g_pool[gg[i] * 64 + 32 + lane], h1[i]);
                if (lane == 0) red1(&g_cnt[gg[i]], 1.0f);
            }
        }
    }
}

// ---------------- final head ----------------
__global__ void k_out(const float* __restrict__ ow, const float* __restrict__ ob,
                      float* __restrict__ out) {
    int lane = threadIdx.x & 31;
    int gidx = (blockIdx.x * blockDim.x + threadIdx.x) >> 5;
    if (gidx >= NGRAPH) return;
    float c = fmaxf(g_cnt[gidx], 1.0f);
    float v = g_pool[gidx * 64 + lane] * __ldg(ow + lane)
            + g_pool[gidx * 64 + 32 + lane] * __ldg(ow + lane + 32);
#pragma unroll
    for (int off = 16; off > 0; off >>= 1) v += __shfl_down_sync(0xffffffffu, v, off);
    if (lane == 0) out[gidx] = fmaxf(v / c + __ldg(ob), 0.f);
}

// ---------------- launch ----------------
extern "C" void kernel_launch(void* const* d_in, const int* in_sizes, int n_in,
                              void* d_out, int out_size) {
    const float* x       = (const float*)d_in[0];
    const int*   ei      = (const int*)  d_in[1];
    const float* ea      = (const float*)d_in[2];
    const int*   batch   = (const int*)  d_in[3];
    const float* lin_w   = (const float*)d_in[4];
    const float* lin_b   = (const float*)d_in[5];
    const float* msg_w1  = (const float*)d_in[6];
    const float* msg_b1  = (const float*)d_in[7];
    const float* msg_g1  = (const float*)d_in[8];
    const float* msg_be1 = (const float*)d_in[9];
    const float* msg_w2  = (const float*)d_in[10];
    const float* msg_b2  = (const float*)d_in[11];
    const float* msg_g2  = (const float*)d_in[12];
    const float* msg_be2 = (const float*)d_in[13];
    const float* upd_w1  = (const float*)d_in[14];
    const float* upd_b1  = (const float*)d_in[15];
    const float* upd_g1  = (const float*)d_in[16];
    const float* upd_be1 = (const float*)d_in[17];
    const float* upd_w2  = (const float*)d_in[18];
    const float* upd_b2  = (const float*)d_in[19];
    const float* upd_g2  = (const float*)d_in[20];
    const float* upd_be2 = (const float*)d_in[21];
    const float* out_w   = (const float*)d_in[22];
    const float* out_b   = (const float*)d_in[23];

    const int* src = ei;
    const int* dst = ei + N_EDGES;

    const double invE = 1.0 / (double)N_EDGES;
    const double invN = 1.0 / (double)N_NODES;

    float* statbase;
    cudaGetSymbolAddress((void**)&statbase, g_stat);

    k_zero<<<512, TB>>>();
    k_lin_proj<<<NB_STAT, TB>>>(x, lin_w, lin_b, msg_w1);

    for (int l = 0; l < NLAYER; l++) {
        const float* W1 = msg_w1 + l * 129 * 32;
        const float* b1 = msg_b1 + l * 32;
        const float* W2 = msg_w2 + l * 32 * 64;
        const float* b2 = msg_b2 + l * 64;
        const float* U1 = upd_w1 + l * 128 * 32;
        const float* v1 = upd_b1 + l * 32;
        const float* U2 = upd_w2 + l * 32 * 64;
        const float* v2 = upd_b2 + l * 64;
        float* m1 = statbase + (l * 4 + 0) * 128;
        float* m2 = statbase + (l * 4 + 1) * 128;
        float* u1 = statbase + (l * 4 + 2) * 128;
        float* u2 = statbase + (l * 4 + 3) * 128;

        k_edge_a<<<NB_STAT, TB>>>(dst, src, ea, W1, b1, W2, m1, l == 0 ? 1 : 0);
        k_edge_b<<<NB_STAT, TB>>>(dst, src, ea, W1, b1, W2, b2,
                                  msg_g1 + l * 32, msg_be1 + l * 32, m1, m2, invE, l);
        k_node_a<<<NB_STAT, TB>>>(U1, v1, msg_g2 + l * 64, msg_be2 + l * 64,
                                  m2, u1, invE, l);
        k_node_b<<<NB_STAT, TB>>>(U2, v2, upd_g1 + l * 32, upd_be1 + l * 32,
                                  u1, u2, invN);
        if (l == NLAYER - 1) {
            k_update_pool<<<NB_STAT, TB>>>(batch, upd_g2 + l * 64, upd_be2 + l * 64,
                                           u2, invN);
        } else {
            k_update_proj<<<NB_STAT, TB>>>(msg_w1 + (l + 1) * 129 * 32,
                                           upd_g2 + l * 64, upd_be2 + l * 64,
                                           u2, invN);
        }
    }

    k_out<<<16, 1024>>>(out_w, out_b, (float*)d_out);
}